// round 10
// baseline (speedup 1.0000x reference)
#include <cuda_runtime.h>
#include <stdint.h>

// Shape fixed for this dataset: B=512 rows, N=16384 residues/row, A atoms/row.
#define N_RES  16384
#define B_MAX  512
#define SPLIT  8
#define SEG4   (N_RES / 4 / SPLIT)    // 512 groups-of-4 per segment
#define TPB    256
#define GPT    (SEG4 / TPB)           // 2 groups per thread
#define HBINS  2048                   // histogram on key bits 31..21
#define CAP    4096                   // compaction capacity (bin members)
#define RCAP   2048                   // resolve capacity (==T16 group)
#define EXCAP  64                     // excluded-ties list capacity

// ---- global scratch (static device allocations; no cudaMalloc) ----
__device__ unsigned short g_key16[(size_t)B_MAX * N_RES];   // 16 MB
__device__ unsigned int   g_hist[(size_t)B_MAX * HBINS];    // 4 MB
__device__ unsigned int   g_done[B_MAX];
__device__ unsigned int   g_flag[B_MAX];                    // 0=pending 1=normal 2=fallback
__device__ unsigned int   g_P[B_MAX];                       // full 32-bit threshold
__device__ unsigned int   g_nexcl[B_MAX];
__device__ unsigned short g_excl[B_MAX][EXCAP];

// Order-preserving float->uint transform (total order == IEEE float compare).
__device__ __forceinline__ unsigned int f2key(float f) {
    unsigned int u = __float_as_uint(f);
    return u ^ ((u & 0x80000000u) ? 0xFFFFFFFFu : 0x80000000u);
}

// Exact replica of reference arithmetic (RN, no FMA contraction).
__device__ __forceinline__ unsigned int dist_key(float cx, float cy, float cz,
                                                 float px, float py, float pz,
                                                 float m) {
    float dx = __fsub_rn(cx, px);
    float dy = __fsub_rn(cy, py);
    float dz = __fsub_rn(cz, pz);
    float ss = __fadd_rn(__fadd_rn(__fmul_rn(dx, dx), __fmul_rn(dy, dy)),
                         __fmul_rn(dz, dz));
    float d = __fsqrt_rn(__fadd_rn(ss, 1e-12f));
    d = __fadd_rn(d, __fmul_rn(__fsub_rn(1.0f, m), 1.0e10f));
    return f2key(d);
}

__device__ __forceinline__ void hist_add(unsigned int* hist, unsigned int bin) {
    unsigned int peers = __match_any_sync(0xFFFFFFFFu, bin);
    int leader = __ffs(peers) - 1;
    if ((threadIdx.x & 31) == leader) atomicAdd(&hist[bin], __popc(peers));
}

__global__ void __launch_bounds__(TPB, 4)
fused_kernel(const float* __restrict__ ca, const float* __restrict__ rmask,
             const float* __restrict__ apos, const float* __restrict__ amask,
             const int* __restrict__ topk_ptr, int A,
             float* __restrict__ out0, float* __restrict__ out1)
{
    __shared__ unsigned int   hist_s[HBINS];       // 8 KB
    __shared__ unsigned short cand_idx[CAP];       // 8 KB
    __shared__ unsigned int   cand_key[RCAP];      // 8 KB
    __shared__ float stage[1024];
    __shared__ float s_cx, s_cy, s_cz;
    __shared__ unsigned int s_wsum[8];
    __shared__ unsigned int s_sub[32];
    __shared__ int s_b11, s_cb11;
    __shared__ unsigned int s_T16;
    __shared__ int s_cb, s_gsz, s_nc, s_last;
    __shared__ unsigned int s_P, s_flagv, s_nex;
    __shared__ unsigned short s_excl[EXCAP];

    const int row = blockIdx.x / SPLIT;
    const int seg = blockIdx.x % SPLIT;
    const int t = threadIdx.x;
    const size_t rowoff = (size_t)row * N_RES;

    for (int i = t; i < HBINS; i += TPB) hist_s[i] = 0;

    // ---- centroid (redundant per block): stage to smem, t0 sequential adds
    //      in exact atom order (bit-exact vs reference).
    const bool can_stage = (A * 4 <= 1024);
    {
        const float* ap = apos + (size_t)row * A * 3;
        const float* am = amask + (size_t)row * A;
        if (can_stage) {
            for (int i = t; i < A * 3; i += TPB) stage[i] = ap[i];
            for (int i = t; i < A; i += TPB)     stage[A * 3 + i] = am[i];
        }
        __syncthreads();
        if (t == 0) {
            float sx = 0.f, sy = 0.f, sz = 0.f, smm = 0.f;
            if (can_stage) {
                #pragma unroll 4
                for (int a = 0; a < A; ++a) {
                    sx  = __fadd_rn(sx,  stage[a * 3 + 0]);
                    sy  = __fadd_rn(sy,  stage[a * 3 + 1]);
                    sz  = __fadd_rn(sz,  stage[a * 3 + 2]);
                    smm = __fadd_rn(smm, stage[A * 3 + a]);
                }
            } else {
                #pragma unroll 4
                for (int a = 0; a < A; ++a) {
                    sx  = __fadd_rn(sx,  ap[a * 3 + 0]);
                    sy  = __fadd_rn(sy,  ap[a * 3 + 1]);
                    sz  = __fadd_rn(sz,  ap[a * 3 + 2]);
                    smm = __fadd_rn(smm, am[a]);
                }
            }
            s_cx = __fdiv_rn(sx, smm);
            s_cy = __fdiv_rn(sy, smm);
            s_cz = __fdiv_rn(sz, smm);
        }
        __syncthreads();
    }
    const float cx = s_cx, cy = s_cy, cz = s_cz;

    // ---- build: full keys + masks stay IN REGISTERS; key16 to scratch.
    const float4* ca4 = reinterpret_cast<const float4*>(ca + rowoff * 3);
    const float4* rm4 = reinterpret_cast<const float4*>(rmask + rowoff);
    uint2* kvw = reinterpret_cast<uint2*>(g_key16 + rowoff);

    unsigned int kr[GPT][4];
    float4 mr[GPT];
    int gidx[GPT];
    #pragma unroll
    for (int i = 0; i < GPT; ++i) {
        int g = seg * SEG4 + t + i * TPB;
        gidx[i] = g;
        float4 v0 = ca4[g * 3 + 0];
        float4 v1 = ca4[g * 3 + 1];
        float4 v2 = ca4[g * 3 + 2];
        float4 m  = rm4[g];
        mr[i] = m;
        kr[i][0] = dist_key(cx, cy, cz, v0.x, v0.y, v0.z, m.x);
        kr[i][1] = dist_key(cx, cy, cz, v0.w, v1.x, v1.y, m.y);
        kr[i][2] = dist_key(cx, cy, cz, v1.z, v1.w, v2.x, m.z);
        kr[i][3] = dist_key(cx, cy, cz, v2.y, v2.z, v2.w, m.w);
        uint2 packed;
        packed.x = (kr[i][0] >> 16) | (kr[i][1] & 0xFFFF0000u);
        packed.y = (kr[i][2] >> 16) | (kr[i][3] & 0xFFFF0000u);
        kvw[g] = packed;
        hist_add(hist_s, kr[i][0] >> 21);
        hist_add(hist_s, kr[i][1] >> 21);
        hist_add(hist_s, kr[i][2] >> 21);
        hist_add(hist_s, kr[i][3] >> 21);
    }
    __syncthreads();

    // flush histogram; release; bump done counter
    unsigned int* gh = g_hist + (size_t)row * HBINS;
    for (int i = t; i < HBINS; i += TPB) {
        unsigned int v = hist_s[i];
        if (v) atomicAdd(&gh[i], v);
    }
    __threadfence();
    if (t == 0) {
        unsigned int old = atomicAdd(&g_done[row], 1u);
        s_last = (old == SPLIT - 1) ? 1 : 0;
    }
    __syncthreads();

    if (s_last) {
        // =================== SELECT (last-arriving block) ===================
        __threadfence();   // acquire all siblings' key16 + hist
        const int kk = *topk_ptr;
        unsigned int flagv = 1u;

        if (kk <= 0) {
            if (t == 0) { g_P[row] = 0u; g_nexcl[row] = 0u; }
        } else if (kk >= N_RES) {
            if (t == 0) { g_P[row] = 0xFFFFFFFFu; g_nexcl[row] = 0u; }
        } else {
            if (t < 32) s_sub[t] = 0;
            if (t == 32) s_nc = 0;
            if (t == 33) { s_b11 = 0; s_cb11 = 0; }
            __syncthreads();

            unsigned short* key16g = g_key16 + rowoff;
            const uint4* kvg = reinterpret_cast<const uint4*>(key16g);

            // scan 2048-bin histogram
            {
                const int w = t >> 5, lane = t & 31;
                const uint4* gh4 = reinterpret_cast<const uint4*>(gh);
                uint4 h0 = gh4[t * 2];
                uint4 h1 = gh4[t * 2 + 1];
                unsigned int hh[8] = {h0.x, h0.y, h0.z, h0.w, h1.x, h1.y, h1.z, h1.w};
                unsigned int local = 0;
                #pragma unroll
                for (int j = 0; j < 8; ++j) local += hh[j];
                unsigned int incl = local;
                #pragma unroll
                for (int o = 1; o < 32; o <<= 1) {
                    unsigned int v = __shfl_up_sync(0xFFFFFFFFu, incl, o);
                    if (lane >= o) incl += v;
                }
                if (lane == 31) s_wsum[w] = incl;
                __syncthreads();
                unsigned int pw = 0;
                for (int j = 0; j < w; ++j) pw += s_wsum[j];
                unsigned int pre = pw + incl - local;
                if ((int)pre < kk && (int)(pre + local) >= kk) {
                    unsigned int cum = pre;
                    #pragma unroll
                    for (int j = 0; j < 8; ++j) {
                        if ((int)(cum + hh[j]) >= kk) { s_b11 = t * 8 + j; s_cb11 = (int)cum; break; }
                        cum += hh[j];
                    }
                }
                __syncthreads();
            }

            // fused sub-histogram + compaction of the chosen bin's members
            {
                const unsigned int b11 = (unsigned int)s_b11;
                #pragma unroll 2
                for (int q = t; q < N_RES / 8; q += TPB) {
                    uint4 v = kvg[q];
                    unsigned int xs[8] = {v.x & 0xFFFFu, v.x >> 16, v.y & 0xFFFFu, v.y >> 16,
                                          v.z & 0xFFFFu, v.z >> 16, v.w & 0xFFFFu, v.w >> 16};
                    #pragma unroll
                    for (int j = 0; j < 8; ++j) {
                        if ((xs[j] >> 5) == b11) {
                            atomicAdd(&s_sub[xs[j] & 31u], 1u);
                            int pos = atomicAdd(&s_nc, 1);
                            if (pos < CAP) cand_idx[pos] = (unsigned short)(q * 8 + j);
                        }
                    }
                }
                __syncthreads();
                if (t == 0) {
                    int cum = s_cb11;
                    #pragma unroll
                    for (int j = 0; j < 32; ++j) {
                        int h = (int)s_sub[j];
                        if (cum + h >= kk) {
                            s_T16 = ((unsigned int)s_b11 << 5) | (unsigned int)j;
                            s_cb = cum;
                            s_gsz = h;
                            break;
                        }
                        cum += h;
                    }
                }
                __syncthreads();
            }

            const unsigned int T16 = s_T16;
            const int krem = kk - s_cb;

            if (krem >= s_gsz) {
                // whole ==T16 group selected: P = max key with this prefix
                if (t == 0) { g_P[row] = (T16 << 16) | 0xFFFFu; g_nexcl[row] = 0u; }
            } else if (s_nc <= CAP && s_gsz <= RCAP) {
                // warp 0: gather ==T16 candidates, recompute full keys, resolve.
                if (t == 0) s_nex = 0;
                __syncthreads();
                if (t < 32) {
                    const int nc = s_nc;
                    int m = 0;
                    for (int base = 0; base < nc; base += 32) {
                        int i = base + t;
                        unsigned short idx = 0;
                        bool p = false;
                        if (i < nc) {
                            idx = cand_idx[i];
                            p = (key16g[idx] == T16);
                        }
                        unsigned int bal = __ballot_sync(0xFFFFFFFFu, p);
                        int rank = __popc(bal & ((1u << t) - 1u));
                        if (p) {
                            int n = (int)idx;
                            float px = __ldg(ca + (rowoff + n) * 3 + 0);
                            float py = __ldg(ca + (rowoff + n) * 3 + 1);
                            float pz = __ldg(ca + (rowoff + n) * 3 + 2);
                            float mm = __ldg(rmask + rowoff + n);
                            cand_key[m + rank] = dist_key(cx, cy, cz, px, py, pz, mm);
                            cand_idx[m + rank] = idx;
                        }
                        m += __popc(bal);
                        __syncwarp();
                    }
                    unsigned int P = T16 << 16;
                    for (int bit = 15; bit >= 0; --bit) {
                        unsigned int C = P | (1u << bit);
                        int c = 0;
                        for (int i = t; i < m; i += 32) c += (cand_key[i] < C);
                        c = __reduce_add_sync(0xFFFFFFFFu, c);
                        if (c < krem) P = C;
                    }
                    int cb2 = 0, eq = 0;
                    for (int i = t; i < m; i += 32) {
                        cb2 += (cand_key[i] < P);
                        eq  += (cand_key[i] == P);
                    }
                    cb2 = __reduce_add_sync(0xFFFFFFFFu, cb2);
                    eq  = __reduce_add_sync(0xFFFFFFFFu, eq);
                    const int req = krem - cb2;     // ==P keys kept (lowest index)
                    const int nex = eq - req;       // ==P keys excluded
                    if (nex <= EXCAP) {
                        for (int i = t; i < m; i += 32) {
                            if (cand_key[i] == P) {
                                int rk = 0;
                                unsigned short my = cand_idx[i];
                                for (int j = 0; j < m; ++j)
                                    rk += (cand_key[j] == P && cand_idx[j] < my);
                                if (rk >= req) {
                                    unsigned int pos = atomicAdd(&s_nex, 1u);
                                    g_excl[row][pos] = my;
                                }
                            }
                        }
                        __syncwarp();
                        if (t == 0) { g_P[row] = P; g_nexcl[row] = s_nex; }
                    } else {
                        // pathological tie flood: rewrite key16 (push out losers),
                        // spinners fall back to key16 <= T16.
                        for (int i = t; i < m; i += 32) {
                            unsigned int x = cand_key[i];
                            bool sel;
                            if (x < P) sel = true;
                            else if (x > P) sel = false;
                            else {
                                int rk = 0;
                                unsigned short my = cand_idx[i];
                                for (int j = 0; j < m; ++j)
                                    rk += (cand_key[j] == P && cand_idx[j] < my);
                                sel = (rk < req);
                            }
                            if (!sel) key16g[cand_idx[i]] = (unsigned short)0xFFFFu;
                        }
                        __syncwarp();
                        if (t == 0) { g_P[row] = (T16 << 16) | 0xFFFFu; g_nexcl[row] = 0u; }
                        flagv = 2u;
                    }
                }
                __syncthreads();
                if (t == 0 && flagv == 1u) { /* already stored */ }
            } else {
                // capacity overflow (effectively never): t0-serial exact fallback.
                if (t == 0) {
                    unsigned int P = T16 << 16;
                    for (int bit = 15; bit >= 0; --bit) {
                        unsigned int C = P | (1u << bit);
                        int c = 0;
                        for (int n = 0; n < N_RES; ++n) {
                            if (key16g[n] == T16) {
                                float px = ca[(rowoff + n) * 3 + 0];
                                float py = ca[(rowoff + n) * 3 + 1];
                                float pz = ca[(rowoff + n) * 3 + 2];
                                float mm = rmask[rowoff + n];
                                c += (dist_key(cx, cy, cz, px, py, pz, mm) < C);
                            }
                        }
                        if (c < krem) P = C;
                    }
                    int cb2 = 0;
                    for (int n = 0; n < N_RES; ++n) {
                        if (key16g[n] == T16) {
                            float px = ca[(rowoff + n) * 3 + 0];
                            float py = ca[(rowoff + n) * 3 + 1];
                            float pz = ca[(rowoff + n) * 3 + 2];
                            float mm = rmask[rowoff + n];
                            cb2 += (dist_key(cx, cy, cz, px, py, pz, mm) < P);
                        }
                    }
                    int req = krem - cb2, seen = 0;
                    for (int n = 0; n < N_RES; ++n) {
                        if (key16g[n] == T16) {
                            float px = ca[(rowoff + n) * 3 + 0];
                            float py = ca[(rowoff + n) * 3 + 1];
                            float pz = ca[(rowoff + n) * 3 + 2];
                            float mm = rmask[rowoff + n];
                            unsigned int x = dist_key(cx, cy, cz, px, py, pz, mm);
                            if (x > P) key16g[n] = (unsigned short)0xFFFFu;
                            else if (x == P) {
                                ++seen;
                                if (seen > req) key16g[n] = (unsigned short)0xFFFFu;
                            }
                        }
                    }
                    g_P[row] = (T16 << 16) | 0xFFFFu;
                    g_nexcl[row] = 0u;
                }
                flagv = 2u;
            }
            __syncthreads();
        }

        // publish: fence, then flag
        if (t == 0) {
            __threadfence();
            atomicExch(&g_flag[row], flagv);
            s_flagv = flagv;
            s_P = g_P[row];
            s_nex = g_nexcl[row];
        }
        __syncthreads();
    } else {
        // =================== SPIN for the row's threshold ===================
        if (t == 0) {
            volatile unsigned int* vf = &g_flag[row];
            unsigned int f;
            while ((f = *vf) == 0u) __nanosleep(128);
            __threadfence();   // acquire P/excl (and key16 in fallback)
            s_flagv = f;
            s_P = g_P[row];
            s_nex = g_nexcl[row];
        }
        __syncthreads();
    }

    const unsigned int P = s_P;
    const unsigned int flagv = s_flagv;
    const unsigned int nex = s_nex;
    if (t < EXCAP) s_excl[t] = (t < (int)nex) ? g_excl[row][t] : (unsigned short)0xFFFFu;
    __syncthreads();

    // ---- write outputs from register-held keys/masks
    float4* o0 = reinterpret_cast<float4*>(out0 + rowoff);
    float4* o1 = reinterpret_cast<float4*>(out1 + rowoff);

    if (flagv == 1u) {
        #pragma unroll
        for (int i = 0; i < GPT; ++i) {
            int g = gidx[i];
            float4 m = mr[i];
            float4 a, bb;
            #pragma unroll
            for (int j = 0; j < 4; ++j) {
                unsigned int x = kr[i][j];
                bool sel = (x < P);
                if (x == P) {
                    sel = true;
                    unsigned short n = (unsigned short)(g * 4 + j);
                    for (unsigned int e = 0; e < nex; ++e)
                        if (s_excl[e] == n) { sel = false; break; }
                }
                float mv = (j == 0) ? m.x : (j == 1) ? m.y : (j == 2) ? m.z : m.w;
                float av = sel ? 0.0f : mv;
                float bv = sel ? 32.0f : __fsub_rn(1.0f, mv);
                if (j == 0) { a.x = av; bb.x = bv; }
                else if (j == 1) { a.y = av; bb.y = bv; }
                else if (j == 2) { a.z = av; bb.z = bv; }
                else { a.w = av; bb.w = bv; }
            }
            o0[g] = a;
            o1[g] = bb;
        }
    } else {
        // fallback: key16 was rewritten; criterion key16 <= T16 (= P>>16)
        const unsigned int T16 = P >> 16;
        const uint2* kvr = reinterpret_cast<const uint2*>(g_key16 + rowoff);
        #pragma unroll
        for (int i = 0; i < GPT; ++i) {
            int g = gidx[i];
            uint2 v = kvr[g];
            unsigned int xs[4] = {v.x & 0xFFFFu, v.x >> 16, v.y & 0xFFFFu, v.y >> 16};
            float4 m = mr[i];
            float4 a, bb;
            a.x = (xs[0] <= T16) ? 0.0f : m.x;
            a.y = (xs[1] <= T16) ? 0.0f : m.y;
            a.z = (xs[2] <= T16) ? 0.0f : m.z;
            a.w = (xs[3] <= T16) ? 0.0f : m.w;
            bb.x = (xs[0] <= T16) ? 32.0f : __fsub_rn(1.0f, m.x);
            bb.y = (xs[1] <= T16) ? 32.0f : __fsub_rn(1.0f, m.y);
            bb.z = (xs[2] <= T16) ? 32.0f : __fsub_rn(1.0f, m.z);
            bb.w = (xs[3] <= T16) ? 32.0f : __fsub_rn(1.0f, m.w);
            o0[g] = a;
            o1[g] = bb;
        }
    }
}

extern "C" void kernel_launch(void* const* d_in, const int* in_sizes, int n_in,
                              void* d_out, int out_size) {
    const float* ca    = (const float*)d_in[0];
    const float* rmask = (const float*)d_in[1];
    const float* apos  = (const float*)d_in[2];
    const float* amask = (const float*)d_in[3];
    const int*   topk  = (const int*)d_in[5];   // [ca, rmask, apos, amask, max_p, top_k]

    const int BN = in_sizes[1];          // B * N
    const int B  = BN / N_RES;
    const int A  = (B > 0) ? in_sizes[3] / B : 64;

    float* out0 = (float*)d_out;
    float* out1 = out0 + (size_t)BN;

    void* histAddr = nullptr; void* doneAddr = nullptr; void* flagAddr = nullptr;
    cudaGetSymbolAddress(&histAddr, g_hist);
    cudaGetSymbolAddress(&doneAddr, g_done);
    cudaGetSymbolAddress(&flagAddr, g_flag);
    cudaMemsetAsync(histAddr, 0, (size_t)B * HBINS * sizeof(unsigned int));
    cudaMemsetAsync(doneAddr, 0, (size_t)B * sizeof(unsigned int));
    cudaMemsetAsync(flagAddr, 0, (size_t)B * sizeof(unsigned int));

    fused_kernel<<<B * SPLIT, TPB>>>(ca, rmask, apos, amask, topk, A, out0, out1);
}

// round 11
// speedup vs baseline: 3.9606x; 3.9606x over previous
#include <cuda_runtime.h>
#include <stdint.h>

// Shape fixed for this dataset: B=512 rows, N=16384 residues/row, A atoms/row.
#define N_RES    16384
#define TPB      384
#define NG4      (N_RES / 4)     // 4096 build groups (4 residues each)
#define NU4      (N_RES / 8)     // 2048 uint4 groups of 8 key16s
#define HBINS    2048            // histogram on key bits 31..21
#define CAP      1024
// dynamic smem: key16 32KB | hist 8KB | cand_idx 4KB | cand_key 4KB = 48KB
#define SMEM_BYTES (32768 + 8192 + 4096 + 4096)

// Order-preserving float->uint transform (total order == IEEE float compare).
__device__ __forceinline__ unsigned int f2key(float f) {
    unsigned int u = __float_as_uint(f);
    return u ^ ((u & 0x80000000u) ? 0xFFFFFFFFu : 0x80000000u);
}

// Exact replica of reference arithmetic (RN, no FMA contraction).
__device__ __forceinline__ unsigned int dist_key(float cx, float cy, float cz,
                                                 float px, float py, float pz,
                                                 float m) {
    float dx = __fsub_rn(cx, px);
    float dy = __fsub_rn(cy, py);
    float dz = __fsub_rn(cz, pz);
    float ss = __fadd_rn(__fadd_rn(__fmul_rn(dx, dx), __fmul_rn(dy, dy)),
                         __fmul_rn(dz, dz));
    float d = __fsqrt_rn(__fadd_rn(ss, 1e-12f));
    d = __fadd_rn(d, __fmul_rn(__fsub_rn(1.0f, m), 1.0e10f));
    return f2key(d);
}

__device__ __forceinline__ void hist_add(unsigned int* hist, unsigned int bin) {
    unsigned int peers = __match_any_sync(0xFFFFFFFFu, bin);
    int leader = __ffs(peers) - 1;
    if ((threadIdx.x & 31) == leader) atomicAdd(&hist[bin], __popc(peers));
}

__global__ void __launch_bounds__(TPB, 4)
spatial_mask_kernel(const float* __restrict__ ca,      // [B, N, 3]
                    const float* __restrict__ rmask,   // [B, N]
                    const float* __restrict__ apos,    // [B, A, 3]
                    const float* __restrict__ amask,   // [B, A]
                    const int*   __restrict__ topk_ptr,
                    int A,
                    float* __restrict__ out0,          // [B, N]
                    float* __restrict__ out1)          // [B, N]
{
    extern __shared__ unsigned char sm[];
    unsigned short* key16    = reinterpret_cast<unsigned short*>(sm);        // [16384]
    unsigned int*   hist     = reinterpret_cast<unsigned int*>(sm + 32768);  // [2048]
    unsigned int*   cand_idx = reinterpret_cast<unsigned int*>(sm + 32768 + 8192);  // [1024]
    unsigned int*   cand_key = reinterpret_cast<unsigned int*>(sm + 32768 + 8192 + 4096); // [1024]

    __shared__ float s_cx, s_cy, s_cz;
    __shared__ int s_k;
    __shared__ unsigned int s_wsum[8];
    __shared__ unsigned int s_sub[32];
    __shared__ int s_b11, s_cb11;
    __shared__ unsigned int s_T16;
    __shared__ int s_cb, s_gsz, s_nc, s_cnt;

    const int b = blockIdx.x;
    const int t = threadIdx.x;
    const size_t row = (size_t)b * N_RES;

    for (int i = t; i < HBINS; i += TPB) hist[i] = 0;
    if (t < 32) s_sub[t] = 0;
    if (t == 32) s_nc = 0;
    if (t == 33) s_cnt = 0;
    if (t == 34) { s_b11 = 0; s_cb11 = 0; }

    // ---- centroid: strict sequential f32 sum in atom order (round-4 form).
    if (t == 0) {
        const float* ap = apos + (size_t)b * A * 3;
        const float* am = amask + (size_t)b * A;
        float sx = 0.f, sy = 0.f, sz = 0.f, smm = 0.f;
        #pragma unroll 4
        for (int a = 0; a < A; ++a) {
            sx  = __fadd_rn(sx,  ap[a * 3 + 0]);
            sy  = __fadd_rn(sy,  ap[a * 3 + 1]);
            sz  = __fadd_rn(sz,  ap[a * 3 + 2]);
            smm = __fadd_rn(smm, am[a]);
        }
        s_cx = __fdiv_rn(sx, smm);
        s_cy = __fdiv_rn(sy, smm);
        s_cz = __fdiv_rn(sz, smm);
        s_k  = *topk_ptr;
    }
    __syncthreads();
    const float cx = s_cx, cy = s_cy, cz = s_cz;
    const int kk = s_k;
    const bool normalK = (kk > 0 && kk < N_RES);

    // ---- build: distances -> 16-bit key prefixes in SMEM + INLINE histogram
    //      (hist atomics hide under DRAM load latency — round-4 proven).
    const float4* ca4 = reinterpret_cast<const float4*>(ca + row * 3);
    const float4* rm4 = reinterpret_cast<const float4*>(rmask + row);
    uint2* key16v = reinterpret_cast<uint2*>(key16);
    #pragma unroll 4
    for (int g = t; g < NG4; g += TPB) {
        float4 v0 = ca4[g * 3 + 0];
        float4 v1 = ca4[g * 3 + 1];
        float4 v2 = ca4[g * 3 + 2];
        float4 m  = rm4[g];
        unsigned int k0 = dist_key(cx, cy, cz, v0.x, v0.y, v0.z, m.x);
        unsigned int k1 = dist_key(cx, cy, cz, v0.w, v1.x, v1.y, m.y);
        unsigned int k2 = dist_key(cx, cy, cz, v1.z, v1.w, v2.x, m.z);
        unsigned int k3 = dist_key(cx, cy, cz, v2.y, v2.z, v2.w, m.w);
        uint2 packed;
        packed.x = (k0 >> 16) | (k1 & 0xFFFF0000u);
        packed.y = (k2 >> 16) | (k3 & 0xFFFF0000u);
        key16v[g] = packed;
        if (normalK) {
            hist_add(hist, k0 >> 21);
            hist_add(hist, k1 >> 21);
            hist_add(hist, k2 >> 21);
            hist_add(hist, k3 >> 21);
        }
    }
    __syncthreads();

    if (normalK) {
        // ---- scan 2048-bin histogram: find 11-bit bin containing the k-th key
        {
            const int w = t >> 5, lane = t & 31;
            unsigned int hh[8];
            unsigned int local = 0, incl = 0;
            if (t < 256) {
                uint4 h0 = reinterpret_cast<uint4*>(hist)[t * 2];
                uint4 h1 = reinterpret_cast<uint4*>(hist)[t * 2 + 1];
                hh[0]=h0.x; hh[1]=h0.y; hh[2]=h0.z; hh[3]=h0.w;
                hh[4]=h1.x; hh[5]=h1.y; hh[6]=h1.z; hh[7]=h1.w;
                #pragma unroll
                for (int j = 0; j < 8; ++j) local += hh[j];
                incl = local;
                #pragma unroll
                for (int o = 1; o < 32; o <<= 1) {
                    unsigned int v = __shfl_up_sync(0xFFFFFFFFu, incl, o);
                    if (lane >= o) incl += v;
                }
                if (lane == 31) s_wsum[w] = incl;
            }
            __syncthreads();
            if (t < 256) {
                unsigned int pw = 0;
                for (int j = 0; j < w; ++j) pw += s_wsum[j];
                unsigned int pre = pw + incl - local;   // exclusive prefix
                if ((int)pre < kk && (int)(pre + local) >= kk) {
                    unsigned int cum = pre;
                    #pragma unroll
                    for (int j = 0; j < 8; ++j) {
                        if ((int)(cum + hh[j]) >= kk) { s_b11 = t * 8 + j; s_cb11 = (int)cum; break; }
                        cum += hh[j];
                    }
                }
            }
            __syncthreads();
        }

        // ---- sub-histogram (5 low bits of key16) within the chosen 11-bit bin
        {
            const unsigned int b11 = (unsigned int)s_b11;
            const uint4* kv = reinterpret_cast<const uint4*>(key16);
            #pragma unroll 2
            for (int q = t; q < NU4; q += TPB) {
                uint4 v = kv[q];
                unsigned int xs[8] = {v.x & 0xFFFFu, v.x >> 16, v.y & 0xFFFFu, v.y >> 16,
                                      v.z & 0xFFFFu, v.z >> 16, v.w & 0xFFFFu, v.w >> 16};
                #pragma unroll
                for (int j = 0; j < 8; ++j) {
                    bool p = ((xs[j] >> 5) == b11);
                    unsigned int act = __ballot_sync(0xFFFFFFFFu, p);
                    if (p) {
                        unsigned int sub = xs[j] & 31u;
                        unsigned int peers = __match_any_sync(act, sub);
                        int leader = __ffs(peers) - 1;
                        if ((t & 31) == leader) atomicAdd(&s_sub[sub], __popc(peers));
                    }
                }
            }
            __syncthreads();
            if (t == 0) {
                int cum = s_cb11;
                #pragma unroll
                for (int j = 0; j < 32; ++j) {
                    int h = (int)s_sub[j];
                    if (cum + h >= kk) {
                        s_T16 = ((unsigned int)s_b11 << 5) | (unsigned int)j;
                        s_cb = cum;
                        s_gsz = h;
                        break;
                    }
                    cum += h;
                }
            }
            __syncthreads();
        }

        const unsigned int T16 = s_T16;
        const int krem = kk - s_cb;
        const bool need_resolve = (krem < s_gsz);

        if (need_resolve) {
            // ---- compact candidates (key16 == T16)
            const uint4* kv = reinterpret_cast<const uint4*>(key16);
            #pragma unroll 2
            for (int q = t; q < NU4; q += TPB) {
                uint4 v = kv[q];
                unsigned int xs[8] = {v.x & 0xFFFFu, v.x >> 16, v.y & 0xFFFFu, v.y >> 16,
                                      v.z & 0xFFFFu, v.z >> 16, v.w & 0xFFFFu, v.w >> 16};
                #pragma unroll
                for (int j = 0; j < 8; ++j) {
                    if (xs[j] == T16) {
                        int pos = atomicAdd(&s_nc, 1);
                        if (pos < CAP) cand_idx[pos] = (unsigned int)(q * 8 + j);
                    }
                }
            }
            __syncthreads();
            const int nc = s_nc;

            if (nc <= CAP) {
                // ---- warp 0: recompute full keys for candidates, resolve low 16 bits
                if (t < 32) {
                    for (int i = t; i < nc; i += 32) {
                        int n = (int)cand_idx[i];
                        float px = __ldg(ca + (row + n) * 3 + 0);
                        float py = __ldg(ca + (row + n) * 3 + 1);
                        float pz = __ldg(ca + (row + n) * 3 + 2);
                        float m  = __ldg(rmask + row + n);
                        cand_key[i] = dist_key(cx, cy, cz, px, py, pz, m);
                    }
                    __syncwarp();
                    unsigned int P = T16 << 16;
                    for (int bit = 15; bit >= 0; --bit) {
                        unsigned int C = P | (1u << bit);
                        int c = 0;
                        for (int i = t; i < nc; i += 32) c += (cand_key[i] < C);
                        c = __reduce_add_sync(0xFFFFFFFFu, c);
                        if (c < krem) P = C;
                    }
                    int cb2 = 0;
                    for (int i = t; i < nc; i += 32) cb2 += (cand_key[i] < P);
                    cb2 = __reduce_add_sync(0xFFFFFFFFu, cb2);
                    const int req = krem - cb2;   // # of ==P keys to keep (by index)
                    for (int i = t; i < nc; i += 32) {
                        unsigned int x = cand_key[i];
                        bool sel;
                        if (x < P) sel = true;
                        else if (x > P) sel = false;
                        else {
                            int rk = 0;
                            unsigned int my = cand_idx[i];
                            for (int j = 0; j < nc; ++j)
                                rk += (cand_key[j] == P && cand_idx[j] < my);
                            sel = (rk < req);   // lowest-index ties kept (top_k stable)
                        }
                        if (!sel) key16[cand_idx[i]] = (unsigned short)0xFFFFu;
                    }
                }
            } else {
                // ---- fallback (cap overflow; effectively never taken): exact,
                //      block-cooperative, recompute full keys each round.
                unsigned int P = T16 << 16;
                for (int bit = 15; bit >= 0; --bit) {
                    if (t == 0) s_cnt = 0;
                    __syncthreads();
                    unsigned int C = P | (1u << bit);
                    int c = 0;
                    for (int n = t; n < N_RES; n += TPB) {
                        if (key16[n] == T16) {
                            float px = __ldg(ca + (row + n) * 3 + 0);
                            float py = __ldg(ca + (row + n) * 3 + 1);
                            float pz = __ldg(ca + (row + n) * 3 + 2);
                            float m  = __ldg(rmask + row + n);
                            c += (dist_key(cx, cy, cz, px, py, pz, m) < C);
                        }
                    }
                    c = __reduce_add_sync(0xFFFFFFFFu, c);
                    if ((t & 31) == 0) atomicAdd(&s_cnt, c);
                    __syncthreads();
                    if (s_cnt < krem) P = C;
                    __syncthreads();
                }
                if (t == 0) {
                    int cb2 = 0;
                    for (int n = 0; n < N_RES; ++n) {
                        if (key16[n] == T16) {
                            float px = ca[(row + n) * 3 + 0];
                            float py = ca[(row + n) * 3 + 1];
                            float pz = ca[(row + n) * 3 + 2];
                            float m  = rmask[row + n];
                            cb2 += (dist_key(cx, cy, cz, px, py, pz, m) < P);
                        }
                    }
                    int req = krem - cb2, seen = 0;
                    for (int n = 0; n < N_RES; ++n) {
                        if (key16[n] == T16) {
                            float px = ca[(row + n) * 3 + 0];
                            float py = ca[(row + n) * 3 + 1];
                            float pz = ca[(row + n) * 3 + 2];
                            float m  = rmask[row + n];
                            unsigned int x = dist_key(cx, cy, cz, px, py, pz, m);
                            if (x > P) key16[n] = (unsigned short)0xFFFFu;
                            else if (x == P) {
                                ++seen;
                                if (seen > req) key16[n] = (unsigned short)0xFFFFu;
                            }
                        }
                    }
                }
            }
        }
    } else if (t == 0) {
        s_T16 = (kk >= N_RES) ? 0xFFFFu : 0u;   // all / none
    }
    __syncthreads();

    // ---- write both masks, 128-bit stores (selected <=> key16 <= T16)
    const unsigned int T16 = s_T16;
    const uint4* kv = reinterpret_cast<const uint4*>(key16);
    float4* o0 = reinterpret_cast<float4*>(out0 + row);
    float4* o1 = reinterpret_cast<float4*>(out1 + row);
    #pragma unroll 2
    for (int q = t; q < NU4; q += TPB) {
        uint4 v = kv[q];
        unsigned int xs[8] = {v.x & 0xFFFFu, v.x >> 16, v.y & 0xFFFFu, v.y >> 16,
                              v.z & 0xFFFFu, v.z >> 16, v.w & 0xFFFFu, v.w >> 16};
        float4 m0 = rm4[q * 2 + 0];
        float4 m1 = rm4[q * 2 + 1];
        float4 a0, a1, b0, b1;
        a0.x = (xs[0] <= T16) ? 0.0f : m0.x;
        a0.y = (xs[1] <= T16) ? 0.0f : m0.y;
        a0.z = (xs[2] <= T16) ? 0.0f : m0.z;
        a0.w = (xs[3] <= T16) ? 0.0f : m0.w;
        a1.x = (xs[4] <= T16) ? 0.0f : m1.x;
        a1.y = (xs[5] <= T16) ? 0.0f : m1.y;
        a1.z = (xs[6] <= T16) ? 0.0f : m1.z;
        a1.w = (xs[7] <= T16) ? 0.0f : m1.w;
        b0.x = (xs[0] <= T16) ? 32.0f : __fsub_rn(1.0f, m0.x);
        b0.y = (xs[1] <= T16) ? 32.0f : __fsub_rn(1.0f, m0.y);
        b0.z = (xs[2] <= T16) ? 32.0f : __fsub_rn(1.0f, m0.z);
        b0.w = (xs[3] <= T16) ? 32.0f : __fsub_rn(1.0f, m0.w);
        b1.x = (xs[4] <= T16) ? 32.0f : __fsub_rn(1.0f, m1.x);
        b1.y = (xs[5] <= T16) ? 32.0f : __fsub_rn(1.0f, m1.y);
        b1.z = (xs[6] <= T16) ? 32.0f : __fsub_rn(1.0f, m1.z);
        b1.w = (xs[7] <= T16) ? 32.0f : __fsub_rn(1.0f, m1.w);
        o0[q * 2 + 0] = a0;
        o0[q * 2 + 1] = a1;
        o1[q * 2 + 0] = b0;
        o1[q * 2 + 1] = b1;
    }
}

extern "C" void kernel_launch(void* const* d_in, const int* in_sizes, int n_in,
                              void* d_out, int out_size) {
    const float* ca    = (const float*)d_in[0];
    const float* rmask = (const float*)d_in[1];
    const float* apos  = (const float*)d_in[2];
    const float* amask = (const float*)d_in[3];
    const int*   topk  = (const int*)d_in[5];   // [ca, rmask, apos, amask, max_p, top_k]

    const int BN = in_sizes[1];          // B * N
    const int B  = BN / N_RES;
    const int A  = (B > 0) ? in_sizes[3] / B : 64;

    float* out0 = (float*)d_out;
    float* out1 = out0 + (size_t)BN;

    cudaFuncSetAttribute(spatial_mask_kernel,
                         cudaFuncAttributeMaxDynamicSharedMemorySize, SMEM_BYTES);
    spatial_mask_kernel<<<B, TPB, SMEM_BYTES>>>(ca, rmask, apos, amask, topk, A,
                                                out0, out1);
}